// round 2
// baseline (speedup 1.0000x reference)
#include <cuda_runtime.h>
#include <cuda_bf16.h>
#include <cstdint>
#include <cstddef>

#define DEV __device__ __forceinline__

constexpr int Dm = 1024, DIm = 2048, Nst = 16, Rr = 64, Bb = 2, Ss = 2048;
constexpr int Mrows = Bb * Ss;        // 4096
constexpr int NC = 16, CL = Ss / NC;  // 16 chunks x 128

// ---- scratch layout ----
constexpr size_t SZ_XS   = (size_t)Mrows * Dm * 2;
constexpr size_t SZ_WIN  = (size_t)2 * DIm * Dm * 2;
constexpr size_t SZ_XZ   = (size_t)Mrows * 2 * DIm * 4;
constexpr size_t SZ_XC   = (size_t)Mrows * DIm * 4;
constexpr size_t SZ_XCB  = (size_t)Mrows * DIm * 2;
constexpr size_t SZ_WXP  = (size_t)96 * DIm * 2;
constexpr size_t SZ_XDBL = (size_t)Mrows * 96 * 4;
constexpr size_t SZ_DT   = (size_t)Mrows * Rr * 2;
constexpr size_t SZ_WDT  = (size_t)DIm * Rr * 2;
constexpr size_t SZ_DEL  = (size_t)Mrows * DIm * 4;
constexpr size_t SZ_MOD  = (size_t)Bb * 3 * Dm * 4;
constexpr size_t SZ_HL   = (size_t)Bb * DIm * NC * Nst * 4;
constexpr size_t SZ_SUMD = (size_t)Bb * DIm * NC * 4;
constexpr size_t SZ_HS   = SZ_HL;
constexpr size_t SZ_Y    = (size_t)Mrows * DIm * 2;
constexpr size_t SZ_WOUT = (size_t)Dm * DIm * 2;

constexpr size_t OFF_XS = 0;
constexpr size_t OFF_WIN  = OFF_XS + SZ_XS;
constexpr size_t OFF_XZ   = OFF_WIN + SZ_WIN;
constexpr size_t OFF_XC   = OFF_XZ + SZ_XZ;
constexpr size_t OFF_XCB  = OFF_XC + SZ_XC;
constexpr size_t OFF_WXP  = OFF_XCB + SZ_XCB;
constexpr size_t OFF_XDBL = OFF_WXP + SZ_WXP;
constexpr size_t OFF_DT   = OFF_XDBL + SZ_XDBL;
constexpr size_t OFF_WDT  = OFF_DT + SZ_DT;
constexpr size_t OFF_DEL  = OFF_WDT + SZ_WDT;
constexpr size_t OFF_MOD  = OFF_DEL + SZ_DEL;
constexpr size_t OFF_HL   = OFF_MOD + SZ_MOD;
constexpr size_t OFF_SUMD = OFF_HL + SZ_HL;
constexpr size_t OFF_HS   = OFF_SUMD + SZ_SUMD;
constexpr size_t OFF_Y    = OFF_HS + SZ_HS;
constexpr size_t OFF_WOUT = OFF_Y + SZ_Y;
constexpr size_t SCRATCH = OFF_WOUT + SZ_WOUT;

__device__ __align__(256) unsigned char g_scratch[SCRATCH];

DEV float siluf(float v) { return v / (1.0f + __expf(-v)); }
DEV float softplusf(float v) { return (v > 20.0f) ? v : log1pf(__expf(v)); }

DEV void cp16(void* s, const void* g) {
    uint32_t sa = (uint32_t)__cvta_generic_to_shared(s);
    asm volatile("cp.async.cg.shared.global [%0], [%1], 16;\n" :: "r"(sa), "l"(g));
}
DEV void cp_commit() { asm volatile("cp.async.commit_group;\n"); }
template <int N> DEV void cp_wait() { asm volatile("cp.async.wait_group %0;\n" :: "n"(N)); }

DEV void ldm4(uint32_t& r0, uint32_t& r1, uint32_t& r2, uint32_t& r3, const void* p) {
    uint32_t s = (uint32_t)__cvta_generic_to_shared(p);
    asm volatile("ldmatrix.sync.aligned.m8n8.x4.shared.b16 {%0,%1,%2,%3}, [%4];"
                 : "=r"(r0), "=r"(r1), "=r"(r2), "=r"(r3) : "r"(s));
}
DEV void mma16(float& c0, float& c1, float& c2, float& c3,
               uint32_t a0, uint32_t a1, uint32_t a2, uint32_t a3, uint32_t b0, uint32_t b1) {
    asm volatile("mma.sync.aligned.m16n8k16.row.col.f32.bf16.bf16.f32 "
                 "{%0,%1,%2,%3},{%4,%5,%6,%7},{%8,%9},{%0,%1,%2,%3};"
                 : "+f"(c0), "+f"(c1), "+f"(c2), "+f"(c3)
                 : "r"(a0), "r"(a1), "r"(a2), "r"(a3), "r"(b0), "r"(b1));
}

__global__ void cvt_bf16_k(const float* __restrict__ in, __nv_bfloat16* __restrict__ out, int n) {
    int i = blockIdx.x * 256 + threadIdx.x;
    if (i < n) out[i] = __float2bfloat16(in[i]);
}
__global__ void cvt_dt_k(const float* __restrict__ xdbl, __nv_bfloat16* __restrict__ dt) {
    int i = blockIdx.x * 256 + threadIdx.x;
    dt[i] = __float2bfloat16(xdbl[(i >> 6) * 96 + (i & 63)]);
}

// adaLN GEMV: mod[b][e] = sum_k silu(c[b][k]) * ada_w[e][k] + ada_b[e]
__global__ __launch_bounds__(256) void ada_k(const float* __restrict__ c,
                                             const float* __restrict__ ada_w,
                                             const float* __restrict__ ada_b,
                                             float* __restrict__ modp) {
    __shared__ float sc[2 * Dm];
    int tid = threadIdx.x, gw0 = blockIdx.x * 8;
    int b = gw0 / (3 * Dm);
    for (int j = tid; j < 2 * Dm; j += 256) sc[j] = siluf(c[b * 2 * Dm + j]);
    __syncthreads();
    int lane = tid & 31, e = (gw0 + (tid >> 5)) % (3 * Dm);
    const float4* wp = (const float4*)(ada_w + (size_t)e * 2 * Dm);
    float acc = 0.0f;
    for (int k = lane; k < (2 * Dm) / 4; k += 32) {
        float4 w = wp[k]; int kk = k * 4;
        acc += sc[kk] * w.x + sc[kk + 1] * w.y + sc[kk + 2] * w.z + sc[kk + 3] * w.w;
    }
    #pragma unroll
    for (int o = 16; o; o >>= 1) acc += __shfl_xor_sync(~0u, acc, o);
    if (lane == 0) modp[b * 3 * Dm + e] = acc + ada_b[e];
}

// LayerNorm + modulate -> xs bf16
__global__ __launch_bounds__(256) void ln_k(const float* __restrict__ x,
                                            const float* __restrict__ ln_w,
                                            const float* __restrict__ ln_b,
                                            const float* __restrict__ modp,
                                            __nv_bfloat16* __restrict__ xs) {
    int r = blockIdx.x, b = r >> 11, tid = threadIdx.x;
    __shared__ float red[8];
    float4 xv = ((const float4*)x)[(size_t)r * 256 + tid];
    float s = xv.x + xv.y + xv.z + xv.w;
    #pragma unroll
    for (int o = 16; o; o >>= 1) s += __shfl_xor_sync(~0u, s, o);
    if ((tid & 31) == 0) red[tid >> 5] = s;
    __syncthreads();
    float tot = 0.0f;
    #pragma unroll
    for (int i = 0; i < 8; i++) tot += red[i];
    float mu = tot * (1.0f / 1024.0f);
    float d0 = xv.x - mu, d1 = xv.y - mu, d2 = xv.z - mu, d3 = xv.w - mu;
    float q = d0 * d0 + d1 * d1 + d2 * d2 + d3 * d3;
    __syncthreads();
    #pragma unroll
    for (int o = 16; o; o >>= 1) q += __shfl_xor_sync(~0u, q, o);
    if ((tid & 31) == 0) red[tid >> 5] = q;
    __syncthreads();
    float qt = 0.0f;
    #pragma unroll
    for (int i = 0; i < 8; i++) qt += red[i];
    float rstd = rsqrtf(qt * (1.0f / 1024.0f) + 1e-5f);
    float4 lw = ((const float4*)ln_w)[tid], lb = ((const float4*)ln_b)[tid];
    const float* shp = modp + b * 3 * Dm;
    float4 sh = ((const float4*)shp)[tid], scv = ((const float4*)(shp + Dm))[tid];
    float o0 = (d0 * rstd * lw.x + lb.x) * (1.0f + scv.x) + sh.x;
    float o1 = (d1 * rstd * lw.y + lb.y) * (1.0f + scv.y) + sh.y;
    float o2 = (d2 * rstd * lw.z + lb.z) * (1.0f + scv.z) + sh.z;
    float o3 = (d3 * rstd * lw.w + lb.w) * (1.0f + scv.w) + sh.w;
    __nv_bfloat162* op = (__nv_bfloat162*)(xs + (size_t)r * Dm + tid * 4);
    op[0] = __floats2bfloat162_rn(o0, o1);
    op[1] = __floats2bfloat162_rn(o2, o3);
}

// bf16 GEMM: C[M,N]=A[M,K]*W[N,K]^T. EPI: 0 plain, 1 softplus(+bias), 2 out=x+gate*acc
template <int BN, int EPI>
__global__ __launch_bounds__(256) void gemm_k(const __nv_bfloat16* __restrict__ A, int lda,
                                              const __nv_bfloat16* __restrict__ Bw, int ldb,
                                              float* __restrict__ C, int ldc, int K,
                                              const float* __restrict__ bias,
                                              const float* __restrict__ xres,
                                              const float* __restrict__ modp) {
    constexpr int BM = 128, BK = 32, LD = BK + 8;
    constexpr int WN = BN / 2, NF = WN / 8;
    constexpr int BCH = BN * BK / 8;
    __shared__ __nv_bfloat16 sA[2][BM * LD];
    __shared__ __nv_bfloat16 sB[2][BN * LD];
    int tid = threadIdx.x, lane = tid & 31, wid = tid >> 5;
    int wm = wid & 3, wn = wid >> 2;
    const __nv_bfloat16* Ag = A + (size_t)blockIdx.y * BM * lda;
    const __nv_bfloat16* Bg = Bw + (size_t)blockIdx.x * BN * ldb;
    float acc[2][NF][4];
    #pragma unroll
    for (int i = 0; i < 2; i++)
        #pragma unroll
        for (int j = 0; j < NF; j++)
            #pragma unroll
            for (int q = 0; q < 4; q++) acc[i][j][q] = 0.0f;
    int KT = K / BK;
    auto load = [&](int st, int kt) {
        #pragma unroll
        for (int i = 0; i < 2; i++) {
            int cid = tid + i * 256, r = cid >> 2, cc = cid & 3;
            cp16(&sA[st][r * LD + cc * 8], Ag + (size_t)r * lda + kt * BK + cc * 8);
        }
        #pragma unroll
        for (int i = 0; i < 2; i++) {
            int cid = tid + i * 256;
            if (cid < BCH) {
                int r = cid >> 2, cc = cid & 3;
                cp16(&sB[st][r * LD + cc * 8], Bg + (size_t)r * ldb + kt * BK + cc * 8);
            }
        }
        cp_commit();
    };
    load(0, 0);
    for (int kt = 0; kt < KT; ++kt) {
        if (kt + 1 < KT) { load((kt + 1) & 1, kt + 1); cp_wait<1>(); }
        else cp_wait<0>();
        __syncthreads();
        int st = kt & 1;
        #pragma unroll
        for (int ks = 0; ks < 2; ++ks) {
            uint32_t a[2][4];
            #pragma unroll
            for (int mf = 0; mf < 2; ++mf) {
                int row = wm * 32 + mf * 16 + (lane & 15);
                ldm4(a[mf][0], a[mf][1], a[mf][2], a[mf][3],
                     &sA[st][row * LD + ks * 16 + (lane >> 4) * 8]);
            }
            #pragma unroll
            for (int nf = 0; nf < NF; ++nf) {
                int n = wn * WN + nf * 8 + (lane >> 2);
                const __nv_bfloat16* bp = &sB[st][n * LD + ks * 16 + (lane & 3) * 2];
                uint32_t b0 = *(const uint32_t*)bp, b1 = *(const uint32_t*)(bp + 8);
                #pragma unroll
                for (int mf = 0; mf < 2; ++mf)
                    mma16(acc[mf][nf][0], acc[mf][nf][1], acc[mf][nf][2], acc[mf][nf][3],
                          a[mf][0], a[mf][1], a[mf][2], a[mf][3], b0, b1);
            }
        }
        __syncthreads();
    }
    #pragma unroll
    for (int mf = 0; mf < 2; ++mf) {
        int r0 = blockIdx.y * BM + wm * 32 + mf * 16 + (lane >> 2), r1 = r0 + 8;
        #pragma unroll
        for (int nf = 0; nf < NF; ++nf) {
            int cb = blockIdx.x * BN + wn * WN + nf * 8 + (lane & 3) * 2;
            float v0 = acc[mf][nf][0], v1 = acc[mf][nf][1];
            float v2 = acc[mf][nf][2], v3 = acc[mf][nf][3];
            if (EPI == 1) {
                float b0v = bias[cb], b1v = bias[cb + 1];
                v0 = softplusf(v0 + b0v); v1 = softplusf(v1 + b1v);
                v2 = softplusf(v2 + b0v); v3 = softplusf(v3 + b1v);
            }
            if (EPI == 2) {
                const float* g0 = modp + (r0 >> 11) * 3 * Dm + 2 * Dm;
                const float* g1 = modp + (r1 >> 11) * 3 * Dm + 2 * Dm;
                v0 = xres[(size_t)r0 * ldc + cb] + g0[cb] * v0;
                v1 = xres[(size_t)r0 * ldc + cb + 1] + g0[cb + 1] * v1;
                v2 = xres[(size_t)r1 * ldc + cb] + g1[cb] * v2;
                v3 = xres[(size_t)r1 * ldc + cb + 1] + g1[cb + 1] * v3;
            }
            *(float2*)&C[(size_t)r0 * ldc + cb] = make_float2(v0, v1);
            *(float2*)&C[(size_t)r1 * ldc + cb] = make_float2(v2, v3);
        }
    }
}

// causal depthwise conv1d + silu
__global__ __launch_bounds__(256) void conv_k(const float* __restrict__ cw,
                                              const float* __restrict__ cbias,
                                              const float* __restrict__ xz,
                                              float* __restrict__ xc,
                                              __nv_bfloat16* __restrict__ xcb) {
    int idx = blockIdx.x * 256 + threadIdx.x;
    int d = idx & (DIm - 1), r = idx >> 11, s = r & (Ss - 1);
    float w0 = cw[d * 4], w1 = cw[d * 4 + 1], w2 = cw[d * 4 + 2], w3 = cw[d * 4 + 3];
    const float* col = xz + (size_t)r * (2 * DIm) + d;
    float acc = cbias[d] + w3 * col[0];
    if (s >= 1) acc += w2 * col[-(2 * DIm)];
    if (s >= 2) acc += w1 * col[-2 * (2 * DIm)];
    if (s >= 3) acc += w0 * col[-3 * (2 * DIm)];
    float v = siluf(acc);
    xc[idx] = v;
    xcb[idx] = __float2bfloat16(v);
}

// scan pass A: per-chunk local scan, h0=0; store chunk-end h and sum(delta)
__global__ __launch_bounds__(256) void scan1_k(const float* __restrict__ A_log,
                                               const float* __restrict__ delta,
                                               const float* __restrict__ xc,
                                               const float* __restrict__ xdbl,
                                               float* __restrict__ hl,
                                               float* __restrict__ sumd) {
    __shared__ float Bs[CL * Nst];
    int tid = threadIdx.x, t = blockIdx.x * 256 + tid;
    int d = t & (DIm - 1), cb = t >> 11, cch = cb & (NC - 1), b = cb >> 4;
    int base = b * Ss + cch * CL;
    for (int j = tid; j < CL * Nst; j += 256)
        Bs[j] = xdbl[(size_t)(base + (j >> 4)) * 96 + Rr + (j & 15)];
    __syncthreads();
    float An[Nst], h[Nst];
    #pragma unroll
    for (int n = 0; n < Nst; n++) { An[n] = -__expf(A_log[d * Nst + n]); h[n] = 0.0f; }
    float sd = 0.0f;
    for (int i = 0; i < CL; i++) {
        size_t idx = (size_t)(base + i) * DIm + d;
        float dl = delta[idx], du = dl * xc[idx];
        sd += dl;
        const float* bp = &Bs[i * Nst];
        #pragma unroll
        for (int n = 0; n < Nst; n++) h[n] = __expf(dl * An[n]) * h[n] + du * bp[n];
    }
    size_t o = ((size_t)(b * DIm + d) * NC + cch) * Nst;
    #pragma unroll
    for (int n = 0; n < Nst; n++) hl[o + n] = h[n];
    sumd[(b * DIm + d) * NC + cch] = sd;
}

// scan pass B: combine chunk transitions -> h at each chunk start
__global__ __launch_bounds__(256) void scan2_k(const float* __restrict__ A_log,
                                               const float* __restrict__ hl,
                                               const float* __restrict__ sumd,
                                               float* __restrict__ hs) {
    int t = blockIdx.x * 256 + threadIdx.x;
    int n = t & 15, d = (t >> 4) & (DIm - 1), b = t >> 15;
    float An = -__expf(A_log[d * Nst + n]);
    float h = 0.0f;
    int cbase = (b * DIm + d) * NC;
    size_t base = (size_t)cbase * Nst + n;
    for (int c = 0; c < NC; c++) {
        hs[base + (size_t)c * Nst] = h;
        h = __expf(An * sumd[cbase + c]) * h + hl[base + (size_t)c * Nst];
    }
}

// scan pass C: replay with true h0, y = (<h,C> + xc*D)*silu(z) -> bf16
__global__ __launch_bounds__(256) void scan3_k(const float* __restrict__ A_log,
                                               const float* __restrict__ D_skip,
                                               const float* __restrict__ delta,
                                               const float* __restrict__ xc,
                                               const float* __restrict__ xdbl,
                                               const float* __restrict__ xz,
                                               const float* __restrict__ hs,
                                               __nv_bfloat16* __restrict__ y) {
    __shared__ float Bs[CL * Nst];
    __shared__ float Cs[CL * Nst];
    int tid = threadIdx.x, t = blockIdx.x * 256 + tid;
    int d = t & (DIm - 1), cb = t >> 11, cch = cb & (NC - 1), b = cb >> 4;
    int base = b * Ss + cch * CL;
    for (int j = tid; j < CL * Nst; j += 256) {
        size_t ro = (size_t)(base + (j >> 4)) * 96 + Rr + (j & 15);
        Bs[j] = xdbl[ro];
        Cs[j] = xdbl[ro + Nst];
    }
    __syncthreads();
    float An[Nst], h[Nst];
    size_t ho = ((size_t)(b * DIm + d) * NC + cch) * Nst;
    #pragma unroll
    for (int n = 0; n < Nst; n++) {
        An[n] = -__expf(A_log[d * Nst + n]);
        h[n] = hs[ho + n];
    }
    float Dv = D_skip[d];
    for (int i = 0; i < CL; i++) {
        size_t idx = (size_t)(base + i) * DIm + d;
        float dl = delta[idx], u = xc[idx], du = dl * u;
        const float* bp = &Bs[i * Nst];
        const float* cp = &Cs[i * Nst];
        float yv = 0.0f;
        #pragma unroll
        for (int n = 0; n < Nst; n++) {
            h[n] = __expf(dl * An[n]) * h[n] + du * bp[n];
            yv += h[n] * cp[n];
        }
        float z = xz[(size_t)(base + i) * (2 * DIm) + DIm + d];
        y[idx] = __float2bfloat16((yv + u * Dv) * siluf(z));
    }
}

extern "C" void kernel_launch(void* const* d_in, const int* in_sizes, int n_in,
                              void* d_out, int out_size) {
    const float* x     = (const float*)d_in[0];
    const float* c     = (const float*)d_in[1];
    // d_in[2] = w (unused by reference)
    const float* ln_w  = (const float*)d_in[3];
    const float* ln_b  = (const float*)d_in[4];
    const float* ada_w = (const float*)d_in[5];
    const float* ada_b = (const float*)d_in[6];
    const float* in_w  = (const float*)d_in[7];
    const float* cw    = (const float*)d_in[8];
    const float* cbias = (const float*)d_in[9];
    const float* xp_w  = (const float*)d_in[10];
    const float* dt_w  = (const float*)d_in[11];
    const float* dt_b  = (const float*)d_in[12];
    const float* A_log = (const float*)d_in[13];
    const float* D_sk  = (const float*)d_in[14];
    const float* out_w = (const float*)d_in[15];
    float* out = (float*)d_out;

    void* sp = nullptr;
    cudaGetSymbolAddress(&sp, g_scratch);
    unsigned char* S = (unsigned char*)sp;
    __nv_bfloat16* xs   = (__nv_bfloat16*)(S + OFF_XS);
    __nv_bfloat16* win  = (__nv_bfloat16*)(S + OFF_WIN);
    float*         xz   = (float*)(S + OFF_XZ);
    float*         xc   = (float*)(S + OFF_XC);
    __nv_bfloat16* xcb  = (__nv_bfloat16*)(S + OFF_XCB);
    __nv_bfloat16* wxp  = (__nv_bfloat16*)(S + OFF_WXP);
    float*         xdbl = (float*)(S + OFF_XDBL);
    __nv_bfloat16* dtb  = (__nv_bfloat16*)(S + OFF_DT);
    __nv_bfloat16* wdt  = (__nv_bfloat16*)(S + OFF_WDT);
    float*         dlt  = (float*)(S + OFF_DEL);
    float*         modp = (float*)(S + OFF_MOD);
    float*         hl   = (float*)(S + OFF_HL);
    float*         sumd = (float*)(S + OFF_SUMD);
    float*         hs   = (float*)(S + OFF_HS);
    __nv_bfloat16* yb   = (__nv_bfloat16*)(S + OFF_Y);
    __nv_bfloat16* wout = (__nv_bfloat16*)(S + OFF_WOUT);

    // weight converts (independent of activations)
    cvt_bf16_k<<<(2 * DIm * Dm + 255) / 256, 256>>>(in_w, win, 2 * DIm * Dm);
    cvt_bf16_k<<<(96 * DIm + 255) / 256, 256>>>(xp_w, wxp, 96 * DIm);
    cvt_bf16_k<<<(DIm * Rr + 255) / 256, 256>>>(dt_w, wdt, DIm * Rr);
    cvt_bf16_k<<<(Dm * DIm + 255) / 256, 256>>>(out_w, wout, Dm * DIm);

    ada_k<<<Bb * 3 * Dm / 8, 256>>>(c, ada_w, ada_b, modp);
    ln_k<<<Mrows, 256>>>(x, ln_w, ln_b, modp, xs);

    // in_proj: [4096,4096] = xs[4096,1024] * win[4096,1024]^T
    gemm_k<128, 0><<<dim3(2 * DIm / 128, Mrows / 128), 256>>>(
        xs, Dm, win, Dm, xz, 2 * DIm, Dm, nullptr, nullptr, nullptr);

    conv_k<<<Mrows * DIm / 256, 256>>>(cw, cbias, xz, xc, xcb);

    // x_proj: [4096,96] = xcb[4096,2048] * wxp[96,2048]^T
    gemm_k<32, 0><<<dim3(96 / 32, Mrows / 128), 256>>>(
        xcb, DIm, wxp, DIm, xdbl, 96, DIm, nullptr, nullptr, nullptr);

    cvt_dt_k<<<Mrows * Rr / 256, 256>>>(xdbl, dtb);

    // dt_proj + softplus: delta[4096,2048]
    gemm_k<128, 1><<<dim3(DIm / 128, Mrows / 128), 256>>>(
        dtb, Rr, wdt, Rr, dlt, DIm, Rr, dt_b, nullptr, nullptr);

    scan1_k<<<Bb * NC * DIm / 256, 256>>>(A_log, dlt, xc, xdbl, hl, sumd);
    scan2_k<<<Bb * DIm * Nst / 256, 256>>>(A_log, hl, sumd, hs);
    scan3_k<<<Bb * NC * DIm / 256, 256>>>(A_log, D_sk, dlt, xc, xdbl, xz, hs, yb);

    // out_proj + residual: out = x + gate * (y * wout^T)
    gemm_k<128, 2><<<dim3(Dm / 128, Mrows / 128), 256>>>(
        yb, DIm, wout, DIm, out, Dm, DIm, nullptr, x, modp);
}